// round 2
// baseline (speedup 1.0000x reference)
#include <cuda_runtime.h>

#define BN 256
#define TN 512
#define CN 128
#define FN 128

// ============================================================
// Conv1D kernel: y[b][t][f] = sum_{k,c} x[b][t+k-1][c] * W[k][c][f] + bias[f]
// grid (T/64, B), block 256. Each thread: 8 rows x 4 cols of output.
// ============================================================
__global__ __launch_bounds__(256) void conv_kernel(
    const float* __restrict__ x,
    const float* __restrict__ W,
    const float* __restrict__ bias,
    float* __restrict__ y)
{
    __shared__ float Xs[64][33];    // [row][cchunk], padded
    __shared__ float Ws[32][128];   // [cchunk][f]

    const int b   = blockIdx.y;
    const int t0  = blockIdx.x * 64;
    const int tid = threadIdx.x;
    const int lane = tid & 31;
    const int warp = tid >> 5;

    float acc[8][4];
    #pragma unroll
    for (int i = 0; i < 8; i++)
        #pragma unroll
        for (int j = 0; j < 4; j++) acc[i][j] = 0.f;

    const int cbase = lane * 4;   // 4 consecutive output channels
    const int rbase = warp * 8;   // 8 consecutive rows

    for (int k = 0; k < 3; k++) {
        for (int c0 = 0; c0 < CN; c0 += 32) {
            // load W chunk: 32 x 128
            #pragma unroll
            for (int q = 0; q < 16; q++) {
                int e  = tid + 256 * q;
                int f  = e & 127;
                int cc = e >> 7;
                Ws[cc][f] = W[((size_t)(k * CN + c0 + cc)) * FN + f];
            }
            // load X chunk: 64 rows x 32 channels (zero-padded in t)
            #pragma unroll
            for (int q = 0; q < 8; q++) {
                int e  = tid + 256 * q;
                int cc = e & 31;
                int r  = e >> 5;
                int t  = t0 + r + k - 1;
                float v = 0.f;
                if (t >= 0 && t < TN)
                    v = x[((size_t)b * TN + t) * CN + c0 + cc];
                Xs[r][cc] = v;
            }
            __syncthreads();
            #pragma unroll
            for (int cc = 0; cc < 32; cc++) {
                const float4 w4 = *(const float4*)&Ws[cc][cbase];
                #pragma unroll
                for (int i = 0; i < 8; i++) {
                    float xv = Xs[rbase + i][cc];
                    acc[i][0] += xv * w4.x;
                    acc[i][1] += xv * w4.y;
                    acc[i][2] += xv * w4.z;
                    acc[i][3] += xv * w4.w;
                }
            }
            __syncthreads();
        }
    }

    float b0 = bias[cbase + 0], b1 = bias[cbase + 1],
          b2 = bias[cbase + 2], b3 = bias[cbase + 3];
    #pragma unroll
    for (int i = 0; i < 8; i++) {
        int t = t0 + rbase + i;
        float4 o;
        o.x = acc[i][0] + b0;
        o.y = acc[i][1] + b1;
        o.z = acc[i][2] + b2;
        o.w = acc[i][3] + b3;
        *(float4*)&y[((size_t)b * TN + t) * FN + cbase] = o;
    }
}

// ============================================================
// Householder QR (LAPACK sgeqrf + sorg2r semantics), in-place on A = d_out.
// One CTA (512 threads) per batch matrix (512 x 128, row-major, lda=128).
// ============================================================
struct QrSmem {
    float sv[512];        // current reflector v (full length, zeros above j)
    float sw[16][128];    // per-warp partial w
    float wt[128];        // tau * (v^T A)
    float red[17];        // norm reduction
    float sc[4];          // 0: alpha, 1: tau, 2: scal
    float stau[128];      // taus for orgqr
};

// Apply H = I - tau v v^T to A[j:512, j+1:128] (all 512 threads participate).
__device__ __forceinline__ void apply_reflector(
    float* __restrict__ A, int j, float tau, QrSmem& s, int lane, int warp, int tid)
{
    const int c0 = lane, c1 = lane + 32, c2 = lane + 64, c3 = lane + 96;
    float p0 = 0.f, p1 = 0.f, p2 = 0.f, p3 = 0.f;
    // w = A^T v  (rows j..511, columns > j)
    #pragma unroll 4
    for (int t = j + warp; t < TN; t += 16) {
        float vt = s.sv[t];
        const float* row = A + (size_t)t * FN;
        if (c0 > j) p0 += vt * row[c0];
        if (c1 > j) p1 += vt * row[c1];
        if (c2 > j) p2 += vt * row[c2];
        if (c3 > j) p3 += vt * row[c3];
    }
    s.sw[warp][c0] = p0;
    s.sw[warp][c1] = p1;
    s.sw[warp][c2] = p2;
    s.sw[warp][c3] = p3;
    __syncthreads();
    if (tid < 128) {
        float acc = 0.f;
        #pragma unroll
        for (int i = 0; i < 16; i++) acc += s.sw[i][tid];
        s.wt[tid] = tau * acc;
    }
    __syncthreads();
    // A -= v * wt^T
    #pragma unroll 4
    for (int t = j + warp; t < TN; t += 16) {
        float vt = s.sv[t];
        float* row = A + (size_t)t * FN;
        if (c0 > j) row[c0] -= vt * s.wt[c0];
        if (c1 > j) row[c1] -= vt * s.wt[c1];
        if (c2 > j) row[c2] -= vt * s.wt[c2];
        if (c3 > j) row[c3] -= vt * s.wt[c3];
    }
}

__global__ __launch_bounds__(512) void qr_kernel(float* __restrict__ Aall)
{
    __shared__ QrSmem s;

    const int b    = blockIdx.x;
    float* A = Aall + (size_t)b * TN * FN;
    const int tid  = threadIdx.x;
    const int lane = tid & 31;
    const int warp = tid >> 5;

    // ---------------- geqrf ----------------
    for (int j = 0; j < FN; j++) {
        // load column j, compute Householder vector (dlarfg)
        float a = 0.f;
        if (tid >= j) a = A[(size_t)tid * FN + j];
        if (tid == j) s.sc[0] = a;
        float sq = (tid > j) ? a * a : 0.f;
        #pragma unroll
        for (int o = 16; o >= 1; o >>= 1) sq += __shfl_xor_sync(0xffffffffu, sq, o);
        if (lane == 0) s.red[warp] = sq;
        __syncthreads();
        if (tid == 0) {
            float xn2 = 0.f;
            #pragma unroll
            for (int i = 0; i < 16; i++) xn2 += s.red[i];
            float alpha = s.sc[0];
            float tau, scal;
            if (xn2 == 0.f) {
                tau = 0.f; scal = 0.f;     // H = I
            } else {
                float beta = -copysignf(sqrtf(alpha * alpha + xn2), alpha);
                tau  = (beta - alpha) / beta;
                scal = 1.f / (alpha - beta);
            }
            s.sc[1] = tau;
            s.sc[2] = scal;
            s.stau[j] = tau;
        }
        __syncthreads();
        const float tau  = s.sc[1];
        const float scal = s.sc[2];
        float v;
        if (tid > j)       v = a * scal;
        else if (tid == j) v = 1.f;
        else               v = 0.f;
        s.sv[tid] = v;
        if (tid > j) A[(size_t)tid * FN + j] = v;   // store reflector
        __syncthreads();
        if (tau != 0.f && j < FN - 1) {
            apply_reflector(A, j, tau, s, lane, warp, tid);
        }
        __syncthreads();
    }

    // ---------------- orgqr (sorg2r, backward) ----------------
    for (int j = FN - 1; j >= 0; j--) {
        const float tau = s.stau[j];
        float v;
        if (tid > j)       v = A[(size_t)tid * FN + j];
        else if (tid == j) v = 1.f;
        else               v = 0.f;
        s.sv[tid] = v;
        __syncthreads();
        if (j < FN - 1 && tau != 0.f) {
            apply_reflector(A, j, tau, s, lane, warp, tid);
        }
        __syncthreads();
        // finalize column j of Q
        float cv;
        if (tid > j)       cv = -tau * v;
        else if (tid == j) cv = 1.f - tau;
        else               cv = 0.f;
        A[(size_t)tid * FN + j] = cv;
        __syncthreads();
    }
}

// ============================================================
extern "C" void kernel_launch(void* const* d_in, const int* in_sizes, int n_in,
                              void* d_out, int out_size)
{
    const float* x    = (const float*)d_in[0];   // [256, 512, 128]
    const float* W    = (const float*)d_in[1];   // [3, 128, 128]
    const float* bias = (const float*)d_in[2];   // [128]
    float* out = (float*)d_out;                  // [256, 512, 128] -> Q

    dim3 cgrid(TN / 64, BN);
    conv_kernel<<<cgrid, 256>>>(x, W, bias, out);   // y -> d_out
    qr_kernel<<<BN, 512>>>(out);                    // QR in-place on d_out
}

// round 3
// speedup vs baseline: 2.8776x; 2.8776x over previous
#include <cuda_runtime.h>

#define BN 256
#define TN 512
#define CN 128
#define FN 128
#define NB 32

typedef unsigned long long ull;

__device__ __forceinline__ ull pk2(float lo, float hi) {
    ull r; asm("mov.b64 %0, {%1, %2};" : "=l"(r) : "f"(lo), "f"(hi)); return r;
}
__device__ __forceinline__ void upk2(ull v, float& lo, float& hi) {
    asm("mov.b64 {%0, %1}, %2;" : "=f"(lo), "=f"(hi) : "l"(v));
}
__device__ __forceinline__ ull fma2(ull a, ull b, ull c) {
    ull d; asm("fma.rn.f32x2 %0, %1, %2, %3;" : "=l"(d) : "l"(a), "l"(b), "l"(c)); return d;
}
__device__ __forceinline__ float wsum(float v) {
    #pragma unroll
    for (int o = 16; o; o >>= 1) v += __shfl_xor_sync(0xffffffffu, v, o);
    return v;
}

// ============================================================
// Conv1D: y[b][t][f] = sum_{k,c} x[b][t+k-1][c] * W[k][c][f] + bias[f]
// ============================================================
__global__ __launch_bounds__(256) void conv_kernel(
    const float* __restrict__ x, const float* __restrict__ W,
    const float* __restrict__ bias, float* __restrict__ y)
{
    __shared__ float Xs[64][33];
    __shared__ float Ws[32][128];

    const int b = blockIdx.y, t0 = blockIdx.x * 64, tid = threadIdx.x;
    const int lane = tid & 31, warp = tid >> 5;
    const int cbase = lane * 4, rbase = warp * 8;

    ull acc2[8][2];
    #pragma unroll
    for (int i = 0; i < 8; i++) { acc2[i][0] = 0ull; acc2[i][1] = 0ull; }

    for (int k = 0; k < 3; k++) {
        for (int c0 = 0; c0 < CN; c0 += 32) {
            #pragma unroll
            for (int q = 0; q < 16; q++) {
                int e = tid + 256 * q, f = e & 127, cc = e >> 7;
                Ws[cc][f] = W[((size_t)(k * CN + c0 + cc)) * FN + f];
            }
            #pragma unroll
            for (int q = 0; q < 8; q++) {
                int e = tid + 256 * q, cc = e & 31, r = e >> 5;
                int t = t0 + r + k - 1;
                float v = 0.f;
                if (t >= 0 && t < TN) v = x[((size_t)b * TN + t) * CN + c0 + cc];
                Xs[r][cc] = v;
            }
            __syncthreads();
            #pragma unroll
            for (int cc = 0; cc < 32; cc++) {
                const ull* wp = (const ull*)&Ws[cc][cbase];
                ull w01 = wp[0], w23 = wp[1];
                #pragma unroll
                for (int i = 0; i < 8; i++) {
                    float xv = Xs[rbase + i][cc];
                    ull xx = pk2(xv, xv);
                    acc2[i][0] = fma2(xx, w01, acc2[i][0]);
                    acc2[i][1] = fma2(xx, w23, acc2[i][1]);
                }
            }
            __syncthreads();
        }
    }
    float b0 = bias[cbase], b1 = bias[cbase+1], b2 = bias[cbase+2], b3 = bias[cbase+3];
    #pragma unroll
    for (int i = 0; i < 8; i++) {
        int t = t0 + rbase + i;
        float4 o; float lo, hi;
        upk2(acc2[i][0], lo, hi); o.x = lo + b0; o.y = hi + b1;
        upk2(acc2[i][1], lo, hi); o.z = lo + b2; o.w = hi + b3;
        *(float4*)&y[((size_t)b * TN + t) * FN + cbase] = o;
    }
}

// ============================================================
// Blocked Householder QR (WY), one CTA per 512x128 matrix.
// SMEM layout (floats):
//  Vp[512*33], Ts[4*32*33], Wm[32*96], Wm2[32*96](also B), taus[128],
//  sred[32], wred[32], scal[8]
// ============================================================
#define VP(t,i)   Vp[(t)*33 + (i)]
#define SM_BYTES 109856

// GEMM1: Wm[i][c] = sum_{t>=o} Vp[t][i]*G[t][colbase+c]
// Tapply: Wm2 = (TRANS ? T^T : T) * Wm
// GEMM2: G[t][colbase+c] -= sum_i Vp[t][i]*Wm2[i][c]
template<int WT, bool TRANS>
__device__ void block_apply(float* G, int o, int colbase,
                            const float* Vp, const float* Tp,
                            float* Wm, float* Wm2, int tid)
{
    const int lane = tid & 31, cw = tid >> 5;
    // ---- GEMM1 ----
    {
        constexpr int CPW = WT >> 4;   // cols per warp
        constexpr int NCP = WT >> 5;   // f32x2 pairs per warp
        ull acc[NCP];
        #pragma unroll
        for (int k = 0; k < NCP; k++) acc[k] = 0ull;
        const float* gcol = G + colbase + cw * CPW;
        #pragma unroll 2
        for (int t = o; t < TN; t++) {
            float v = VP(t, lane);
            ull vv = pk2(v, v);
            const ull* g = (const ull*)(gcol + (size_t)t * FN);
            #pragma unroll
            for (int k = 0; k < NCP; k++) acc[k] = fma2(vv, g[k], acc[k]);
        }
        ull* wout = (ull*)(Wm + lane * 96 + cw * CPW);
        #pragma unroll
        for (int k = 0; k < NCP; k++) wout[k] = acc[k];
    }
    __syncthreads();
    // ---- T apply ----
    {
        constexpr int NP = WT >> 1;    // pairs per row of W
        for (int pos = tid; pos < 32 * NP; pos += 512) {
            int i = pos / NP, cp = pos - i * NP;
            ull acc = 0ull;
            #pragma unroll
            for (int j = 0; j < 32; j++) {
                float tv = TRANS ? Tp[j * 33 + i] : Tp[i * 33 + j];
                acc = fma2(pk2(tv, tv), *(const ull*)(Wm + j * 96 + 2 * cp), acc);
            }
            *(ull*)(Wm2 + i * 96 + 2 * cp) = acc;
        }
    }
    __syncthreads();
    // ---- GEMM2 ----
    {
        constexpr int NCG = WT >> 3;   // 8-col groups
        const int npos = ((TN - o) >> 1) * NCG;
        for (int pos = tid; pos < npos; pos += 512) {
            int tg = pos / NCG, cg = pos - tg * NCG;
            int t0 = o + 2 * tg;
            float* g0 = G + (size_t)t0 * FN + colbase + cg * 8;
            float* g1 = g0 + FN;
            ull a0[4], a1[4];
            #pragma unroll
            for (int k = 0; k < 4; k++) { a0[k] = ((ull*)g0)[k]; a1[k] = ((ull*)g1)[k]; }
            #pragma unroll 2
            for (int i = 0; i < 32; i++) {
                float v0 = VP(t0, i), v1 = VP(t0 + 1, i);
                ull nv0 = pk2(-v0, -v0), nv1 = pk2(-v1, -v1);
                const ull* w = (const ull*)(Wm2 + i * 96 + cg * 8);
                #pragma unroll
                for (int k = 0; k < 4; k++) {
                    a0[k] = fma2(nv0, w[k], a0[k]);
                    a1[k] = fma2(nv1, w[k], a1[k]);
                }
            }
            #pragma unroll
            for (int k = 0; k < 4; k++) { ((ull*)g0)[k] = a0[k]; ((ull*)g1)[k] = a1[k]; }
        }
    }
    __syncthreads();
}

__device__ void panel_factor(float* Vp, float* taus, float* sred, float* wred,
                             float* scal, int o, int tid)
{
    const int lane = tid & 31, w = tid >> 5;
    for (int i = 0; i < NB; i++) {
        const int prow = o + i;
        float val = 0.f;
        if (tid >= prow) val = VP(tid, i);
        if (tid == prow) scal[0] = val;
        float sq = (tid > prow) ? val * val : 0.f;
        sq = wsum(sq);
        if (lane == 0) sred[w] = sq;
        __syncthreads();
        if (tid == 0) {
            float s2 = 0.f;
            #pragma unroll
            for (int k = 0; k < 16; k++) s2 += sred[k];
            float alpha = scal[0], tau, sc;
            if (s2 == 0.f) { tau = 0.f; sc = 0.f; }
            else {
                float beta = -copysignf(sqrtf(alpha * alpha + s2), alpha);
                tau = (beta - alpha) / beta;
                sc = 1.f / (alpha - beta);
            }
            scal[1] = tau; scal[2] = sc; taus[o + i] = tau;
        }
        __syncthreads();
        const float tau = scal[1], sc = scal[2];
        if (tid > prow)       VP(tid, i) = val * sc;
        else if (tid == prow) VP(tid, i) = 1.f;
        __syncthreads();
        if (tau != 0.f && i < NB - 1) {
            // w_c = v^T * panel_col_c for c > i (warp w owns c = w, w+16)
            const int c0 = w, c1 = w + 16;
            float p0 = 0.f, p1 = 0.f;
            for (int t = prow + lane; t < TN; t += 32) {
                float vi = VP(t, i);
                p0 += vi * VP(t, c0);
                p1 += vi * VP(t, c1);
            }
            p0 = wsum(p0); p1 = wsum(p1);
            if (lane == 0) { wred[c0] = p0; wred[c1] = p1; }
            __syncthreads();
            float tw = tau * wred[lane];
            if (lane > i) {
                for (int t = prow + w; t < TN; t += 16)
                    VP(t, lane) -= tw * VP(t, i);
            }
            __syncthreads();
        }
    }
}

__device__ void build_T(const float* Vp, float* B, float* Tp, const float* taus,
                        int o, int tid)
{
    const int lane = tid & 31, w = tid >> 5;
    // B[j][i] = v_j^T v_i  (j < i), sum over t >= o+i
    for (int i = 1; i < NB; i++) {
        for (int j = w; j < i; j += 16) {
            float p = 0.f;
            for (int t = o + i + lane; t < TN; t += 32)
                p += VP(t, j) * VP(t, i);
            p = wsum(p);
            if (lane == 0) B[j * 32 + i] = p;
        }
    }
    __syncthreads();
    if (w == 0) {
        for (int i = 0; i < NB; i++) {
            float ti = taus[o + i];
            float a = 0.f;
            for (int k = 0; k < i; k++)
                a += Tp[lane * 33 + k] * B[k * 32 + i];   // T[lane][k]=0 for k<lane
            float tv = (lane < i) ? -ti * a : (lane == i ? ti : 0.f);
            Tp[lane * 33 + i] = tv;
            __syncwarp();
        }
    }
    __syncthreads();
}

// orgqr panel formation: Q[:, o:o+32] = E_p - V * (T * L0^T)
__device__ void form_panel(float* G, const float* Vp, const float* Tp,
                           float* M, int o, int tid)
{
    const int lane = tid & 31, w = tid >> 5;
    for (int pos = tid; pos < 32 * 32; pos += 512) {
        int i = pos >> 5, c = pos & 31;
        float a = 0.f;
        #pragma unroll 8
        for (int j = 0; j < 32; j++)
            a += Tp[i * 33 + j] * VP(o + c, j);   // T[i][j]=0 j<i; V above diag = 0
        M[i * 32 + c] = a;
    }
    __syncthreads();
    for (int t = o + w; t < TN; t += 16) {
        float q = (t == o + lane) ? 1.f : 0.f;
        #pragma unroll 8
        for (int j = 0; j < 32; j++)
            q -= VP(t, j) * M[j * 32 + lane];
        G[(size_t)t * FN + o + lane] = q;
    }
    for (int idx = tid; idx < o * 32; idx += 512) {
        int t = idx >> 5, c = idx & 31;
        G[(size_t)t * FN + o + c] = 0.f;
    }
    __syncthreads();
}

__global__ __launch_bounds__(512, 2) void qr_kernel(float* __restrict__ Aall)
{
    extern __shared__ float sm[];
    float* Vp   = sm;                 // 512*33 = 16896
    float* Ts   = Vp + 16896;         // 4*32*33 = 4224
    float* Wm   = Ts + 4224;          // 3072
    float* Wm2  = Wm + 3072;          // 3072 (also B)
    float* taus = Wm2 + 3072;         // 128
    float* sred = taus + 128;         // 32
    float* wred = sred + 32;          // 32
    float* scal = wred + 32;          // 8

    const int b = blockIdx.x;
    float* A = Aall + (size_t)b * TN * FN;
    const int tid = threadIdx.x;
    const int lane = tid & 31, w = tid >> 5;

    // ---------------- geqrf (blocked) ----------------
    for (int p = 0; p < 4; p++) {
        const int o = p * 32;
        for (int t = o + w; t < TN; t += 16)
            VP(t, lane) = A[(size_t)t * FN + o + lane];
        __syncthreads();
        panel_factor(Vp, taus, sred, wred, scal, o, tid);
        // zero junk above the diagonal of the panel
        for (int pos = tid; pos < 32 * 32; pos += 512) {
            int i = pos >> 5, r = pos & 31;
            if (r < i) VP(o + r, i) = 0.f;
        }
        __syncthreads();
        float* Tp = Ts + p * 1056;
        build_T(Vp, Wm2, Tp, taus, o, tid);
        if (p == 0)      block_apply<96, true>(A, 0,  32,  Vp, Tp, Wm, Wm2, tid);
        else if (p == 1) block_apply<64, true>(A, 32, 64,  Vp, Tp, Wm, Wm2, tid);
        else if (p == 2) block_apply<32, true>(A, 64, 96,  Vp, Tp, Wm, Wm2, tid);
        // write V panel back (rows >= o), zeros above diag included
        for (int t = o + w; t < TN; t += 16)
            A[(size_t)t * FN + o + lane] = VP(t, lane);
        __syncthreads();
    }

    // ---------------- orgqr (blocked, backward) ----------------
    for (int p = 3; p >= 0; p--) {
        const int o = p * 32;
        for (int t = o + w; t < TN; t += 16)
            VP(t, lane) = A[(size_t)t * FN + o + lane];
        __syncthreads();
        const float* Tp = Ts + p * 1056;
        if (p == 0)      block_apply<96, false>(A, 0,  32, Vp, Tp, Wm, Wm2, tid);
        else if (p == 1) block_apply<64, false>(A, 32, 64, Vp, Tp, Wm, Wm2, tid);
        else if (p == 2) block_apply<32, false>(A, 64, 96, Vp, Tp, Wm, Wm2, tid);
        form_panel(A, Vp, Tp, Wm, o, tid);
    }
}

// ============================================================
extern "C" void kernel_launch(void* const* d_in, const int* in_sizes, int n_in,
                              void* d_out, int out_size)
{
    const float* x    = (const float*)d_in[0];
    const float* W    = (const float*)d_in[1];
    const float* bias = (const float*)d_in[2];
    float* out = (float*)d_out;

    cudaFuncSetAttribute(qr_kernel, cudaFuncAttributeMaxDynamicSharedMemorySize, SM_BYTES);

    dim3 cgrid(TN / 64, BN);
    conv_kernel<<<cgrid, 256>>>(x, W, bias, out);
    qr_kernel<<<BN, 512, SM_BYTES>>>(out);
}

// round 4
// speedup vs baseline: 3.2036x; 1.1133x over previous
#include <cuda_runtime.h>

#define BN 256
#define TN 512
#define CN 128
#define FN 128
#define NB 32

typedef unsigned long long ull;

__device__ __forceinline__ ull pk2(float lo, float hi) {
    ull r; asm("mov.b64 %0, {%1, %2};" : "=l"(r) : "f"(lo), "f"(hi)); return r;
}
__device__ __forceinline__ void upk2(ull v, float& lo, float& hi) {
    asm("mov.b64 {%0, %1}, %2;" : "=f"(lo), "=f"(hi) : "l"(v));
}
__device__ __forceinline__ ull fma2(ull a, ull b, ull c) {
    ull d; asm("fma.rn.f32x2 %0, %1, %2, %3;" : "=l"(d) : "l"(a), "l"(b), "l"(c)); return d;
}
__device__ __forceinline__ float wsum(float v) {
    #pragma unroll
    for (int o = 16; o; o >>= 1) v += __shfl_xor_sync(0xffffffffu, v, o);
    return v;
}

// ============================================================
// Conv1D: y[b][t][f] = sum_{k,c} x[b][t+k-1][c] * W[k][c][f] + bias[f]
// ============================================================
__global__ __launch_bounds__(256) void conv_kernel(
    const float* __restrict__ x, const float* __restrict__ W,
    const float* __restrict__ bias, float* __restrict__ y)
{
    __shared__ float Xs[64][33];
    __shared__ float Ws[32][128];

    const int b = blockIdx.y, t0 = blockIdx.x * 64, tid = threadIdx.x;
    const int lane = tid & 31, warp = tid >> 5;
    const int cbase = lane * 4, rbase = warp * 8;

    ull acc2[8][2];
    #pragma unroll
    for (int i = 0; i < 8; i++) { acc2[i][0] = 0ull; acc2[i][1] = 0ull; }

    for (int k = 0; k < 3; k++) {
        for (int c0 = 0; c0 < CN; c0 += 32) {
            #pragma unroll
            for (int q = 0; q < 16; q++) {
                int e = tid + 256 * q, f = e & 127, cc = e >> 7;
                Ws[cc][f] = W[((size_t)(k * CN + c0 + cc)) * FN + f];
            }
            #pragma unroll
            for (int q = 0; q < 8; q++) {
                int e = tid + 256 * q, cc = e & 31, r = e >> 5;
                int t = t0 + r + k - 1;
                float v = 0.f;
                if (t >= 0 && t < TN) v = x[((size_t)b * TN + t) * CN + c0 + cc];
                Xs[r][cc] = v;
            }
            __syncthreads();
            #pragma unroll
            for (int cc = 0; cc < 32; cc++) {
                const ull* wp = (const ull*)&Ws[cc][cbase];
                ull w01 = wp[0], w23 = wp[1];
                #pragma unroll
                for (int i = 0; i < 8; i++) {
                    float xv = Xs[rbase + i][cc];
                    ull xx = pk2(xv, xv);
                    acc2[i][0] = fma2(xx, w01, acc2[i][0]);
                    acc2[i][1] = fma2(xx, w23, acc2[i][1]);
                }
            }
            __syncthreads();
        }
    }
    float b0 = bias[cbase], b1 = bias[cbase+1], b2 = bias[cbase+2], b3 = bias[cbase+3];
    #pragma unroll
    for (int i = 0; i < 8; i++) {
        int t = t0 + rbase + i;
        float4 o; float lo, hi;
        upk2(acc2[i][0], lo, hi); o.x = lo + b0; o.y = hi + b1;
        upk2(acc2[i][1], lo, hi); o.z = lo + b2; o.w = hi + b3;
        *(float4*)&y[((size_t)b * TN + t) * FN + cbase] = o;
    }
}

// ============================================================
// Blocked Householder QR (WY), one CTA per 512x128 matrix.
// Vp stored stride-32 with XOR swizzle: conflict-free for both row and
// column access patterns.
// ============================================================
#define VP(t,i)   Vp[((t) << 5) | (((i) ^ (t)) & 31)]
#define W2STRIDE  120   /* 32 rows x (NCGmax=12 groups x 10 floats) */

// GEMM1: Wm[i][c] = sum_{t>=o} V[t][i]*G[t][colbase+c]   (SMEM-staged)
// Tapply: Wm2 = -(T^op * Wm)  (group-10 padded layout, negated)
// GEMM2: G[t][colbase+c] += sum_i V[t][i]*Wm2[i][c]
template<int WT, bool TRANS>
__device__ void block_apply(float* __restrict__ G, int o, int colbase,
                            const float* __restrict__ Vp, const float* __restrict__ Tp,
                            float* __restrict__ Wm, float* __restrict__ Wm2, int tid)
{
    const int lane = tid & 31, w = tid >> 5;
    constexpr int NU = WT / 32;      // ull per warp-row in GEMM1 (3,2,1)
    constexpr int HW = WT / 2;       // ull per staged row
    constexpr int TU = 16 * HW;      // ull per 16-row tile
    ull* Gs = (ull*)Wm2;             // staging buffer overlays Wm2

    // ---- GEMM1 (SMEM staged, acc in registers across tiles) ----
    ull acc[NU];
    #pragma unroll
    for (int k = 0; k < NU; k++) acc[k] = 0ull;
    const int ntiles = (TN - o) >> 4;
    for (int tile = 0; tile < ntiles; tile++) {
        const int t0 = o + (tile << 4);
        for (int u = tid; u < TU; u += 512) {
            int r = u / HW, c = u - r * HW;
            Gs[u] = *(const ull*)(G + (size_t)(t0 + r) * FN + colbase + 2 * c);
        }
        __syncthreads();
        #pragma unroll
        for (int r = 0; r < 16; r++) {
            float v = VP(t0 + r, lane);
            ull vv = pk2(v, v);
            const ull* g = Gs + r * HW + w * NU;
            #pragma unroll
            for (int k = 0; k < NU; k++) acc[k] = fma2(vv, g[k], acc[k]);
        }
        __syncthreads();
    }
    {
        ull* wout = (ull*)(Wm + lane * 96) + w * NU;
        #pragma unroll
        for (int k = 0; k < NU; k++) wout[k] = acc[k];
    }
    __syncthreads();

    // ---- Tapply: Wm2[i][cg*10 + k] = -(T^op Wm)[i][cg*8 + k] ----
    {
        constexpr int NCG = WT / 8;
        for (int pos = tid; pos < 32 * NCG * 4; pos += 512) {
            int i = pos / (NCG * 4);
            int rem = pos - i * (NCG * 4);
            int cg = rem >> 2, k = rem & 3;
            int c = cg * 8 + 2 * k;
            ull a = 0ull;
            #pragma unroll
            for (int j = 0; j < 32; j++) {
                float tv = TRANS ? Tp[j * 33 + i] : Tp[i * 33 + j];
                a = fma2(pk2(-tv, -tv), *(const ull*)(Wm + j * 96 + c), a);
            }
            *(ull*)(Wm2 + i * W2STRIDE + cg * 10 + 2 * k) = a;
        }
    }
    __syncthreads();

    // ---- GEMM2: 4 rows x 8 cols register tiles ----
    {
        constexpr int NCG = WT / 8;
        const int npos = ((TN - o) >> 2) * NCG;
        for (int pos = tid; pos < npos; pos += 512) {
            int tg = pos / NCG, cg = pos - tg * NCG;
            int t0 = o + (tg << 2);
            float* gp = G + (size_t)t0 * FN + colbase + cg * 8;
            ull a[4][4];
            #pragma unroll
            for (int r = 0; r < 4; r++) {
                ulonglong2 q0 = ((const ulonglong2*)(gp + r * FN))[0];
                ulonglong2 q1 = ((const ulonglong2*)(gp + r * FN))[1];
                a[r][0] = q0.x; a[r][1] = q0.y; a[r][2] = q1.x; a[r][3] = q1.y;
            }
            #pragma unroll 2
            for (int i = 0; i < 32; i++) {
                const ull* wp = (const ull*)(Wm2 + i * W2STRIDE + cg * 10);
                ull w0 = wp[0], w1 = wp[1], w2 = wp[2], w3 = wp[3];
                #pragma unroll
                for (int r = 0; r < 4; r++) {
                    float v = VP(t0 + r, i);
                    ull vv = pk2(v, v);
                    a[r][0] = fma2(vv, w0, a[r][0]);
                    a[r][1] = fma2(vv, w1, a[r][1]);
                    a[r][2] = fma2(vv, w2, a[r][2]);
                    a[r][3] = fma2(vv, w3, a[r][3]);
                }
            }
            #pragma unroll
            for (int r = 0; r < 4; r++) {
                ulonglong2 q0, q1;
                q0.x = a[r][0]; q0.y = a[r][1]; q1.x = a[r][2]; q1.y = a[r][3];
                ((ulonglong2*)(gp + r * FN))[0] = q0;
                ((ulonglong2*)(gp + r * FN))[1] = q1;
            }
        }
    }
    __syncthreads();
}

__device__ void panel_factor(float* Vp, float* taus, float* sred, float* wred,
                             float* scal, int o, int tid)
{
    const int lane = tid & 31, w = tid >> 5;
    for (int i = 0; i < NB; i++) {
        const int prow = o + i;
        float val = 0.f;
        if (tid >= prow) val = VP(tid, i);
        if (tid == prow) scal[0] = val;
        float sq = (tid > prow) ? val * val : 0.f;
        sq = wsum(sq);
        if (lane == 0) sred[w] = sq;
        __syncthreads();
        if (tid == 0) {
            float s2 = 0.f;
            #pragma unroll
            for (int k = 0; k < 16; k++) s2 += sred[k];
            float alpha = scal[0], tau, sc;
            if (s2 == 0.f) { tau = 0.f; sc = 0.f; }
            else {
                float beta = -copysignf(sqrtf(alpha * alpha + s2), alpha);
                tau = (beta - alpha) / beta;
                sc = 1.f / (alpha - beta);
            }
            scal[1] = tau; scal[2] = sc; taus[o + i] = tau;
        }
        __syncthreads();
        const float tau = scal[1], sc = scal[2];
        if (tid > prow)       VP(tid, i) = val * sc;
        else if (tid == prow) VP(tid, i) = 1.f;
        __syncthreads();
        if (tau != 0.f && i < NB - 1) {
            const int c0 = w, c1 = w + 16;
            float p0 = 0.f, p1 = 0.f;
            for (int t = prow + lane; t < TN; t += 32) {
                float vi = VP(t, i);
                p0 += vi * VP(t, c0);
                p1 += vi * VP(t, c1);
            }
            p0 = wsum(p0); p1 = wsum(p1);
            if (lane == 0) { wred[c0] = p0; wred[c1] = p1; }
            __syncthreads();
            float tw = tau * wred[lane];
            if (lane > i) {
                for (int t = prow + w; t < TN; t += 16)
                    VP(t, lane) -= tw * VP(t, i);
            }
            __syncthreads();
        }
    }
}

__device__ void build_T(const float* Vp, float* B, float* Tp, const float* taus,
                        int o, int tid)
{
    const int lane = tid & 31, w = tid >> 5;
    for (int i = 1; i < NB; i++) {
        for (int j = w; j < i; j += 16) {
            float p = 0.f;
            for (int t = o + i + lane; t < TN; t += 32)
                p += VP(t, j) * VP(t, i);
            p = wsum(p);
            if (lane == 0) B[j * 32 + i] = p;
        }
    }
    __syncthreads();
    if (w == 0) {
        for (int i = 0; i < NB; i++) {
            float ti = taus[o + i];
            float a = 0.f;
            for (int k = 0; k < i; k++)
                a += Tp[lane * 33 + k] * B[k * 32 + i];
            float tv = (lane < i) ? -ti * a : (lane == i ? ti : 0.f);
            Tp[lane * 33 + i] = tv;
            __syncwarp();
        }
    }
    __syncthreads();
}

// orgqr panel formation: Q[:, o:o+32] = E_p - V * (T * L0^T)
__device__ void form_panel(float* G, const float* Vp, const float* Tp,
                           float* M, int o, int tid)
{
    const int lane = tid & 31, w = tid >> 5;
    for (int pos = tid; pos < 32 * 32; pos += 512) {
        int i = pos >> 5, c = pos & 31;
        float a = 0.f;
        #pragma unroll 8
        for (int j = 0; j < 32; j++)
            a += Tp[i * 33 + j] * VP(o + c, j);
        M[i * 32 + c] = a;
    }
    __syncthreads();
    for (int t = o + w; t < TN; t += 16) {
        float q = (t == o + lane) ? 1.f : 0.f;
        #pragma unroll 8
        for (int j = 0; j < 32; j++)
            q -= VP(t, j) * M[j * 32 + lane];
        G[(size_t)t * FN + o + lane] = q;
    }
    for (int idx = tid; idx < o * 32; idx += 512) {
        int t = idx >> 5, c = idx & 31;
        G[(size_t)t * FN + o + c] = 0.f;
    }
    __syncthreads();
}

// SMEM layout (floats):
//  Vp 16384 | Ts 4224 | Wm 3072 | Wm2 3840 | taus 128 | sred 16 | wred 32 | scal 4
#define SM_FLOATS (16384 + 4224 + 3072 + 3840 + 128 + 16 + 32 + 4)
#define SM_BYTES  (SM_FLOATS * 4)

__global__ __launch_bounds__(512, 2) void qr_kernel(float* __restrict__ Aall)
{
    extern __shared__ float sm[];
    float* Vp   = sm;                 // 16384
    float* Ts   = Vp + 16384;         // 4224
    float* Wm   = Ts + 4224;          // 3072
    float* Wm2  = Wm + 3072;          // 3840 (also GEMM1 staging + build_T B)
    float* taus = Wm2 + 3840;         // 128
    float* sred = taus + 128;         // 16
    float* wred = sred + 16;          // 32
    float* scal = wred + 32;          // 4

    const int b = blockIdx.x;
    float* A = Aall + (size_t)b * TN * FN;
    const int tid = threadIdx.x;
    const int lane = tid & 31, w = tid >> 5;

    // ---------------- geqrf (blocked) ----------------
    for (int p = 0; p < 4; p++) {
        const int o = p * 32;
        for (int t = o + w; t < TN; t += 16)
            VP(t, lane) = A[(size_t)t * FN + o + lane];
        __syncthreads();
        panel_factor(Vp, taus, sred, wred, scal, o, tid);
        for (int pos = tid; pos < 32 * 32; pos += 512) {
            int i = pos >> 5, r = pos & 31;
            if (r < i) VP(o + r, i) = 0.f;
        }
        __syncthreads();
        float* Tp = Ts + p * 1056;
        build_T(Vp, Wm2, Tp, taus, o, tid);
        if (p == 0)      block_apply<96, true>(A, 0,  32,  Vp, Tp, Wm, Wm2, tid);
        else if (p == 1) block_apply<64, true>(A, 32, 64,  Vp, Tp, Wm, Wm2, tid);
        else if (p == 2) block_apply<32, true>(A, 64, 96,  Vp, Tp, Wm, Wm2, tid);
        if (p != 3) {   // panel 3 stays resident in SMEM for orgqr
            for (int t = o + w; t < TN; t += 16)
                A[(size_t)t * FN + o + lane] = VP(t, lane);
            __syncthreads();
        }
    }

    // ---------------- orgqr (blocked, backward) ----------------
    for (int p = 3; p >= 0; p--) {
        const int o = p * 32;
        if (p != 3) {
            for (int t = o + w; t < TN; t += 16)
                VP(t, lane) = A[(size_t)t * FN + o + lane];
            __syncthreads();
        }
        const float* Tp = Ts + p * 1056;
        if (p == 0)      block_apply<96, false>(A, 0,  32, Vp, Tp, Wm, Wm2, tid);
        else if (p == 1) block_apply<64, false>(A, 32, 64, Vp, Tp, Wm, Wm2, tid);
        else if (p == 2) block_apply<32, false>(A, 64, 96, Vp, Tp, Wm, Wm2, tid);
        form_panel(A, Vp, Tp, Wm, o, tid);
    }
}

// ============================================================
extern "C" void kernel_launch(void* const* d_in, const int* in_sizes, int n_in,
                              void* d_out, int out_size)
{
    const float* x    = (const float*)d_in[0];
    const float* W    = (const float*)d_in[1];
    const float* bias = (const float*)d_in[2];
    float* out = (float*)d_out;

    cudaFuncSetAttribute(qr_kernel, cudaFuncAttributeMaxDynamicSharedMemorySize, SM_BYTES);

    dim3 cgrid(TN / 64, BN);
    conv_kernel<<<cgrid, 256>>>(x, W, bias, out);
    qr_kernel<<<BN, 512, SM_BYTES>>>(out);
}